// round 3
// baseline (speedup 1.0000x reference)
#include <cuda_runtime.h>
#include <cstdint>

#define BB 256
#define CC 2048
#define HWN 49
#define KK 16
typedef unsigned long long ull;

// Static device scratch
__device__ __align__(16) float g_part[BB * 8 * 784];  // [b][q][k*49+hw]
__device__ __align__(16) float g_fc16[BB * 784];      // [b][hw*16+k], BN'd, /49
__device__ __align__(16) float g_wT[CC * KK];         // [c][16]
__device__ float g_binv[KK], g_boff[KK];

__device__ __forceinline__ ull ffma2(ull a, ull b, ull c) {
    ull d;
    asm("fma.rn.f32x2 %0, %1, %2, %3;" : "=l"(d) : "l"(a), "l"(b), "l"(c));
    return d;
}
__device__ __forceinline__ ull pack2(float x, float y) {
    ull r;
    asm("mov.b64 %0, {%1, %2};" : "=l"(r) : "f"(x), "f"(y));
    return r;
}
__device__ __forceinline__ void unpack2(ull v, float& x, float& y) {
    asm("mov.b64 {%0, %1}, %2;" : "=f"(x), "=f"(y) : "l"(v));
}

// ============================================================================
// K0: transpose weights -> g_wT[c][16]; BN constants (1/49 folded)
// ============================================================================
__global__ void k0_prep(const float* __restrict__ w16,
                        const float* __restrict__ bng, const float* __restrict__ bnb,
                        const float* __restrict__ bnm, const float* __restrict__ bnv) {
    int idx = blockIdx.x * 256 + threadIdx.x;
    if (idx < CC * KK) {
        int c = idx >> 4, k = idx & 15;
        g_wT[idx] = w16[k * CC + c];
    }
    if (blockIdx.x == 0 && threadIdx.x < KK) {
        int k = threadIdx.x;
        float iv = bng[k] * rsqrtf(bnv[k] + 1e-5f);
        g_binv[k] = iv * (1.0f / 49.0f);
        g_boff[k] = (bnb[k] - bnm[k] * iv) * (1.0f / 49.0f);
    }
}

// ============================================================================
// K1: partial conv. Block = (c-slice q of 256, b), 128 threads (4 warps x 64c).
// Lanes = hw. Software-pipelined loads (featmap + uniform weight LDG.128).
// ============================================================================
__global__ __launch_bounds__(128) void k1_conv(const float* __restrict__ fm) {
    __shared__ float red[4 * 784];
    const int b = blockIdx.y, q = blockIdx.x;
    const int tid = threadIdx.x;
    const int lane = tid & 31, wid = tid >> 5;

    const float* fmc = fm + (size_t)b * (CC * HWN) + (size_t)(q * 256 + wid * 64) * HWN;
    const float* wq = g_wT + (q * 256 + wid * 64) * KK;

    ull acc0[8], acc1[8];
#pragma unroll
    for (int i = 0; i < 8; i++) { acc0[i] = 0ull; acc1[i] = 0ull; }

    // prologue: load c=0 operands
    float v0 = fmc[lane];
    float v1 = (lane < 17) ? fmc[lane + 32] : 0.0f;
    ulonglong2 wA = ((const ulonglong2*)wq)[0];
    ulonglong2 wB = ((const ulonglong2*)wq)[1];
    ulonglong2 wC = ((const ulonglong2*)wq)[2];
    ulonglong2 wD = ((const ulonglong2*)wq)[3];

#pragma unroll 4
    for (int j = 0; j < 63; j++) {
        // prefetch j+1
        float nv0 = fmc[(j + 1) * HWN + lane];
        float nv1 = (lane < 17) ? fmc[(j + 1) * HWN + lane + 32] : 0.0f;
        const ulonglong2* nw = (const ulonglong2*)(wq + (j + 1) * KK);
        ulonglong2 nA = nw[0], nB = nw[1], nC = nw[2], nD = nw[3];

        ull vv0 = pack2(v0, v0), vv1 = pack2(v1, v1);
        acc0[0] = ffma2(wA.x, vv0, acc0[0]);  acc1[0] = ffma2(wA.x, vv1, acc1[0]);
        acc0[1] = ffma2(wA.y, vv0, acc0[1]);  acc1[1] = ffma2(wA.y, vv1, acc1[1]);
        acc0[2] = ffma2(wB.x, vv0, acc0[2]);  acc1[2] = ffma2(wB.x, vv1, acc1[2]);
        acc0[3] = ffma2(wB.y, vv0, acc0[3]);  acc1[3] = ffma2(wB.y, vv1, acc1[3]);
        acc0[4] = ffma2(wC.x, vv0, acc0[4]);  acc1[4] = ffma2(wC.x, vv1, acc1[4]);
        acc0[5] = ffma2(wC.y, vv0, acc0[5]);  acc1[5] = ffma2(wC.y, vv1, acc1[5]);
        acc0[6] = ffma2(wD.x, vv0, acc0[6]);  acc1[6] = ffma2(wD.x, vv1, acc1[6]);
        acc0[7] = ffma2(wD.y, vv0, acc0[7]);  acc1[7] = ffma2(wD.y, vv1, acc1[7]);

        v0 = nv0; v1 = nv1; wA = nA; wB = nB; wC = nC; wD = nD;
    }
    {   // epilogue c = 63
        ull vv0 = pack2(v0, v0), vv1 = pack2(v1, v1);
        acc0[0] = ffma2(wA.x, vv0, acc0[0]);  acc1[0] = ffma2(wA.x, vv1, acc1[0]);
        acc0[1] = ffma2(wA.y, vv0, acc0[1]);  acc1[1] = ffma2(wA.y, vv1, acc1[1]);
        acc0[2] = ffma2(wB.x, vv0, acc0[2]);  acc1[2] = ffma2(wB.x, vv1, acc1[2]);
        acc0[3] = ffma2(wB.y, vv0, acc0[3]);  acc1[3] = ffma2(wB.y, vv1, acc1[3]);
        acc0[4] = ffma2(wC.x, vv0, acc0[4]);  acc1[4] = ffma2(wC.x, vv1, acc1[4]);
        acc0[5] = ffma2(wC.y, vv0, acc0[5]);  acc1[5] = ffma2(wC.y, vv1, acc1[5]);
        acc0[6] = ffma2(wD.x, vv0, acc0[6]);  acc1[6] = ffma2(wD.x, vv1, acc1[6]);
        acc0[7] = ffma2(wD.y, vv0, acc0[7]);  acc1[7] = ffma2(wD.y, vv1, acc1[7]);
    }

    // per-warp partials -> smem
#pragma unroll
    for (int kp = 0; kp < 8; kp++) {
        float a, c0;
        unpack2(acc0[kp], a, c0);
        red[wid * 784 + (2 * kp) * 49 + lane] = a;
        red[wid * 784 + (2 * kp + 1) * 49 + lane] = c0;
        if (lane < 17) {
            float x, y;
            unpack2(acc1[kp], x, y);
            red[wid * 784 + (2 * kp) * 49 + lane + 32] = x;
            red[wid * 784 + (2 * kp + 1) * 49 + lane + 32] = y;
        }
    }
    __syncthreads();

    float* dst = g_part + ((size_t)b * 8 + q) * 784;
    for (int o = tid; o < 784; o += 128) {
        float s = (red[o] + red[784 + o]) + (red[2 * 784 + o] + red[3 * 784 + o]);
        dst[o] = s;
    }
}

// ============================================================================
// K1b: reduce 8 c-slices, apply BN, relayout [k*49+hw] -> [hw*16+k]
// ============================================================================
__global__ __launch_bounds__(784) void k1b_reduce() {
    const int b = blockIdx.x;
    const int o = threadIdx.x;
    const float* src = g_part + (size_t)b * 8 * 784;
    float s = 0.0f;
#pragma unroll
    for (int qq = 0; qq < 8; qq++) s += src[qq * 784 + o];
    int k = o / 49;
    int hw = o - k * 49;
    g_fc16[b * 784 + hw * 16 + k] = s * g_binv[k] + g_boff[k];
}

// ============================================================================
// K2: bilinear. Block = (c-tile 512, b), 256 threads, 2 c/thread.
// featmap tile staged to dynamic smem; fc16 read directly from GLOBAL via
// warp-uniform LDG.128 (coalescer dedups -> 1 wavefront, L1-resident).
// ============================================================================
__global__ __launch_bounds__(256) void k2_bilinear(const float* __restrict__ fm,
                                                   float* __restrict__ out) {
    extern __shared__ float fms[];  // 512*49 floats = 100352 B

    const int tid = threadIdx.x;
    const int b = blockIdx.y;
    const int cbase = blockIdx.x * 512;

    const float* fmb = fm + (size_t)b * (CC * HWN) + (size_t)cbase * HWN;
    for (int i = tid; i < (512 * HWN) / 4; i += 256)
        ((float4*)fms)[i] = ((const float4*)fmb)[i];
    __syncthreads();

    const float* rowA = &fms[tid * HWN];
    const float* rowB = &fms[(tid + 256) * HWN];
    const ulonglong2* fcb = (const ulonglong2*)(g_fc16 + b * 784);

    ull accA[8], accB[8];
#pragma unroll
    for (int i = 0; i < 8; i++) { accA[i] = 0ull; accB[i] = 0ull; }

#pragma unroll 7
    for (int hw = 0; hw < HWN; hw++) {
        ulonglong2 q0 = fcb[hw * 4 + 0];  // uniform LDG.128, k 0..3
        ulonglong2 q1 = fcb[hw * 4 + 1];  // k 4..7
        ulonglong2 q2 = fcb[hw * 4 + 2];  // k 8..11
        ulonglong2 q3 = fcb[hw * 4 + 3];  // k 12..15
        float va = rowA[hw], vb = rowB[hw];
        ull vva = pack2(va, va), vvb = pack2(vb, vb);
        accA[0] = ffma2(q0.x, vva, accA[0]);  accB[0] = ffma2(q0.x, vvb, accB[0]);
        accA[1] = ffma2(q0.y, vva, accA[1]);  accB[1] = ffma2(q0.y, vvb, accB[1]);
        accA[2] = ffma2(q1.x, vva, accA[2]);  accB[2] = ffma2(q1.x, vvb, accB[2]);
        accA[3] = ffma2(q1.y, vva, accA[3]);  accB[3] = ffma2(q1.y, vvb, accB[3]);
        accA[4] = ffma2(q2.x, vva, accA[4]);  accB[4] = ffma2(q2.x, vvb, accB[4]);
        accA[5] = ffma2(q2.y, vva, accA[5]);  accB[5] = ffma2(q2.y, vvb, accB[5]);
        accA[6] = ffma2(q3.x, vva, accA[6]);  accB[6] = ffma2(q3.x, vvb, accB[6]);
        accA[7] = ffma2(q3.y, vva, accA[7]);  accB[7] = ffma2(q3.y, vvb, accB[7]);
    }

    float* obA = out + (size_t)b * 32768 + cbase + tid;
    float* obB = obA + 256;
#pragma unroll
    for (int kp = 0; kp < 8; kp++) {
        float x, y;
        unpack2(accA[kp], x, y);
        obA[(2 * kp) * 2048] = x;
        obA[(2 * kp + 1) * 2048] = y;
        unpack2(accB[kp], x, y);
        obB[(2 * kp) * 2048] = x;
        obB[(2 * kp + 1) * 2048] = y;
    }
}

extern "C" void kernel_launch(void* const* d_in, const int* in_sizes, int n_in,
                              void* d_out, int out_size) {
    const float* fm  = (const float*)d_in[0];  // [256,2048,7,7]
    const float* w16 = (const float*)d_in[1];  // [16,2048]
    const float* bng = (const float*)d_in[2];
    const float* bnb = (const float*)d_in[3];
    const float* bnm = (const float*)d_in[4];
    const float* bnv = (const float*)d_in[5];
    float* out = (float*)d_out;

    static bool attr_done = false;
    // cudaFuncSetAttribute is not a stream op; safe during capture. Idempotent.
    cudaFuncSetAttribute(k2_bilinear, cudaFuncAttributeMaxDynamicSharedMemorySize,
                         512 * HWN * (int)sizeof(float));
    (void)attr_done;

    k0_prep<<<(CC * KK + 255) / 256, 256>>>(w16, bng, bnb, bnm, bnv);
    dim3 g1(8, BB);
    k1_conv<<<g1, 128>>>(fm);
    k1b_reduce<<<BB, 784>>>();
    dim3 g2(4, BB);
    k2_bilinear<<<g2, 256, 512 * HWN * (int)sizeof(float)>>>(fm, out);
}